// round 11
// baseline (speedup 1.0000x reference)
#include <cuda_runtime.h>
#include <cuda_bf16.h>

// N=256 rows, W=512 positions, 3 channels, K=64 buckets.
#define N_ROWS 256
#define WLEN   512
#define K      64
#define BT     128           // 4 warps; 4 elements / thread
#define EPT    4
#define NW     4

// Cross-CTA combine scratch (device globals: no allocations allowed).
__device__ float        g_partial[N_ROWS * 3];
__device__ unsigned int g_cnt[N_ROWS];          // zero-init; atomicInc(...,2) self-resets

// One CTA per (row, channel). ZERO-ATOMIC histogram: per-warp ballot counting.
// Each of 4 rounds ballots the 6 bucket bits + flag; lane L owns buckets
// {L, L+32} and popcounts its match masks into packed (pos|neg<<16) registers.
// Warp 0 merges the 4 warp histograms, scans, and bakes per-bucket float
// weights  wP=2PP+cP-p, wN=2PN+cN-q, wAll=2(PP+PN)+cP+cN-W.  Then per element:
// one LDS.128 + FFMAs:
//   S_pp = 2Σ_pos h*wP,  S_nn = 2Σ_neg h*wN,  S_all = 2Σ h*wAll
//   loss = S_pp/(p²-p+1) + (1-(S_all-S_pp-S_nn)/(2pq+1)) + S_nn/(q²-q+1)
// Last CTA of each row (fence + atomicInc) folds the 3 channel partials.
__global__ void __launch_bounds__(BT)
icl_kernel(const float* __restrict__ a_gt, const float* __restrict__ s_gt,
           const float* __restrict__ e_gt, const float* __restrict__ a_h,
           const float* __restrict__ s_h,  const float* __restrict__ e_h,
           float* __restrict__ out)
{
    __shared__ int    cnt[K][NW];   // [bucket][warp] packed pos|neg<<16
    __shared__ float4 metaf[K];     // {wP, wN, wAll, pad}
    __shared__ int    totalSh;      // packed totals p | q<<16
    __shared__ float  red[3][NW];

    const int n    = blockIdx.x;
    const int c    = blockIdx.y;
    const int tid  = threadIdx.x;
    const int wid  = tid >> 5, lane = tid & 31;
    const int base = n * WLEN;

    const float* __restrict__ gt = (c == 0) ? a_gt : (c == 1) ? s_gt : e_gt;
    const float* __restrict__ ht = (c == 0) ? a_h  : (c == 1) ? s_h  : e_h;

    // ---- global loads (2 LDG.128, front-batched) ----
    const float4 h4 = ((const float4*)(ht + base))[tid];
    const float4 g4 = ((const float4*)(gt + base))[tid];

    const float h[EPT]  = { h4.x, h4.y, h4.z, h4.w };
    const float gv[EPT] = { g4.x, g4.y, g4.z, g4.w };

    int  b[EPT];
    bool f[EPT];
    #pragma unroll
    for (int i = 0; i < EPT; ++i) {
        int bi = (int)(h[i] * (float)K);
        b[i] = (bi > K - 1) ? (K - 1) : bi;
        f[i] = (gv[i] > 0.5f);
    }

    // ---- ballot histogram: registers only, no atomics, no zeroing ----
    // Lane L owns buckets L (bit5=0) and L+32 (bit5=1).
    int cl = 0, ch = 0;   // packed pos|neg<<16 counts for owned buckets
    #pragma unroll
    for (int i = 0; i < EPT; ++i) {
        const int bi = b[i];
        const unsigned r0 = __ballot_sync(0xFFFFFFFFu, bi & 1);
        const unsigned r1 = __ballot_sync(0xFFFFFFFFu, bi & 2);
        const unsigned r2 = __ballot_sync(0xFFFFFFFFu, bi & 4);
        const unsigned r3 = __ballot_sync(0xFFFFFFFFu, bi & 8);
        const unsigned r4 = __ballot_sync(0xFFFFFFFFu, bi & 16);
        const unsigned r5 = __ballot_sync(0xFFFFFFFFu, bi & 32);
        const unsigned rf = __ballot_sync(0xFFFFFFFFu, f[i]);

        unsigned m = (lane & 1  ? r0 : ~r0);
        m &=         (lane & 2  ? r1 : ~r1);
        m &=         (lane & 4  ? r2 : ~r2);
        m &=         (lane & 8  ? r3 : ~r3);
        m &=         (lane & 16 ? r4 : ~r4);
        const unsigned mLo = m & ~r5;          // bucket L
        const unsigned mHi = m &  r5;          // bucket L+32
        cl += __popc(mLo & rf) + (__popc(mLo & ~rf) << 16);
        ch += __popc(mHi & rf) + (__popc(mHi & ~rf) << 16);
    }
    cnt[lane][wid]      = cl;
    cnt[lane + 32][wid] = ch;
    __syncthreads();                                   // BAR 1: histograms visible

    // ---- single-warp merge + packed scan + float-weight writeback ----
    if (wid == 0) {
        // lane L handles buckets 2L, 2L+1 (blocked order for the scan)
        const int4 m0 = ((const int4*)cnt)[2 * lane];      // cnt[2L][0..3]
        const int4 m1 = ((const int4*)cnt)[2 * lane + 1];  // cnt[2L+1][0..3]
        const int x0 = m0.x + m0.y + m0.z + m0.w;
        const int x1 = m1.x + m1.y + m1.z + m1.w;
        const int tsum = x0 + x1;

        int incv = tsum;
        #pragma unroll
        for (int off = 1; off < 32; off <<= 1) {
            const int v = __shfl_up_sync(0xFFFFFFFFu, incv, off);
            if (lane >= off) incv += v;
        }
        const int total = __shfl_sync(0xFFFFFFFFu, incv, 31);
        const int p = total & 0xFFFF;
        const int q = total >> 16;

        int pr = incv - tsum;                          // packed exclusive prefix
        {
            const int cP = x0 & 0xFFFF, cN = x0 >> 16;
            const int PP = pr & 0xFFFF, PN = pr >> 16;
            metaf[2 * lane] = make_float4(
                (float)(2 * PP + cP - p),
                (float)(2 * PN + cN - q),
                (float)(2 * (PP + PN) + (cP + cN) - WLEN), 0.0f);
            pr += x0;
        }
        {
            const int cP = x1 & 0xFFFF, cN = x1 >> 16;
            const int PP = pr & 0xFFFF, PN = pr >> 16;
            metaf[2 * lane + 1] = make_float4(
                (float)(2 * PP + cP - p),
                (float)(2 * PN + cN - q),
                (float)(2 * (PP + PN) + (cP + cN) - WLEN), 0.0f);
        }
        if (lane == 0) totalSh = total;
    }
    __syncthreads();                                   // BAR 2: weights visible

    // ---- per-element fp32 contributions: LDS.128 + FFMAs ----
    float app = 0.0f, ann = 0.0f, aall = 0.0f;
    #pragma unroll
    for (int i = 0; i < EPT; ++i) {
        const float4 w = metaf[b[i]];
        if (f[i]) app += h[i] * w.x;
        else      ann += h[i] * w.y;
        aall += h[i] * w.z;
    }

    // ---- fp32 reduce: intra-warp shuffles, then 4-entry cross-warp ----
    #pragma unroll
    for (int off = 16; off > 0; off >>= 1) {
        app  += __shfl_down_sync(0xFFFFFFFFu, app,  off);
        ann  += __shfl_down_sync(0xFFFFFFFFu, ann,  off);
        aall += __shfl_down_sync(0xFFFFFFFFu, aall, off);
    }
    if (lane == 0) { red[0][wid] = app; red[1][wid] = ann; red[2][wid] = aall; }
    __syncthreads();                                   // BAR 3

    // ---- tail + last-block combine ----
    if (tid == 0) {
        float Ap = 0.0f, An = 0.0f, Aa = 0.0f;
        #pragma unroll
        for (int w = 0; w < NW; ++w) { Ap += red[0][w]; An += red[1][w]; Aa += red[2][w]; }
        const int total = totalSh;
        const float pf = (float)(total & 0xFFFF);
        const float qf = (float)(total >> 16);
        const float Apn = Aa - Ap - An;
        const float c1 = (2.0f * Ap)  / (pf * (pf - 1.0f) + 1.0f);
        const float c2 = 1.0f - (2.0f * Apn) / (2.0f * pf * qf + 1.0f);
        const float c3 = (2.0f * An)  / (qf * (qf - 1.0f) + 1.0f);

        g_partial[n * 3 + c] = c1 + c2 + c3;
        __threadfence();
        const unsigned int old = atomicInc(&g_cnt[n], 2u);   // wraps 2 -> 0 (replay-safe)
        if (old == 2u) {
            volatile float* gp = g_partial;
            out[n] = gp[n * 3 + 0] + gp[n * 3 + 1] + gp[n * 3 + 2];
        }
    }
}

extern "C" void kernel_launch(void* const* d_in, const int* in_sizes, int n_in,
                              void* d_out, int out_size)
{
    const float* a_gt = (const float*)d_in[0];
    const float* s_gt = (const float*)d_in[1];
    const float* e_gt = (const float*)d_in[2];
    const float* a_h  = (const float*)d_in[3];
    const float* s_h  = (const float*)d_in[4];
    const float* e_h  = (const float*)d_in[5];
    float* out = (float*)d_out;

    dim3 grid(N_ROWS, 3);
    icl_kernel<<<grid, BT>>>(a_gt, s_gt, e_gt, a_h, s_h, e_h, out);
}

// round 12
// speedup vs baseline: 1.3349x; 1.3349x over previous
#include <cuda_runtime.h>
#include <cuda_bf16.h>

// N=256 rows, W=512 positions, 3 channels, K=64 buckets.
#define N_ROWS 256
#define WLEN   512
#define K      64
#define BT     384           // 12 warps = 3 groups x 4 warps (one group per channel)
#define GW     4             // warps per group

// One CTA per ROW; channel g handled by warp-group g (warps 4g..4g+3), fully
// independent via named barriers. Per group: ballot histogram (no atomics),
// group-warp-0 merge+scan bakes per-bucket float weights
//   wP=2PP+cP-p, wN=2PN+cN-q, wAll=2(PP+PN)+cP+cN-W,
// then per element one LDS.128 + FFMAs:
//   S_pp=2Σ_pos h*wP, S_nn=2Σ_neg h*wN, S_all=2Σ h*wAll
//   loss_c = S_pp/(p²-p+1) + (1-(S_all-S_pp-S_nn)/(2pq+1)) + S_nn/(q²-q+1)
// One final full barrier; tid0 folds 12 warp-partials -> out[n]. No global
// scratch, no fences, no cross-CTA combine.
__global__ void __launch_bounds__(BT)
icl_kernel(const float* __restrict__ a_gt, const float* __restrict__ s_gt,
           const float* __restrict__ e_gt, const float* __restrict__ a_h,
           const float* __restrict__ s_h,  const float* __restrict__ e_h,
           float* __restrict__ out)
{
    __shared__ int    cnt[3][K][GW];   // [ch][bucket][warp-in-group] packed pos|neg<<16
    __shared__ float4 metaf[3][K];     // [ch][bucket] {wP, wN, wAll, pad}
    __shared__ int    totalSh[3];      // packed totals p | q<<16 per channel
    __shared__ float  red[3][GW][3];   // [ch][warp-in-group][{pp,nn,all}]

    const int n    = blockIdx.x;
    const int tid  = threadIdx.x;
    const int wid  = tid >> 5, lane = tid & 31;
    const int g    = wid >> 2;          // channel 0..2
    const int wg   = wid & 3;           // warp within group
    const int gtid = (wg << 5) | lane;  // 0..127 within group
    const int base = n * WLEN;

    const float* __restrict__ gt = (g == 0) ? a_gt : (g == 1) ? s_gt : e_gt;
    const float* __restrict__ ht = (g == 0) ? a_h  : (g == 1) ? s_h  : e_h;

    // ---- global loads (2 LDG.128 per thread, front-batched) ----
    const float4 h4 = ((const float4*)(ht + base))[gtid];
    const float4 g4 = ((const float4*)(gt + base))[gtid];

    const float h[4]  = { h4.x, h4.y, h4.z, h4.w };
    const float gv[4] = { g4.x, g4.y, g4.z, g4.w };

    int  b[4];
    bool f[4];
    #pragma unroll
    for (int i = 0; i < 4; ++i) {
        int bi = (int)(h[i] * (float)K);
        b[i] = (bi > K - 1) ? (K - 1) : bi;
        f[i] = (gv[i] > 0.5f);
    }

    // ---- ballot histogram: registers only ----
    int cl = 0, ch = 0;   // packed pos|neg<<16 counts for buckets {lane, lane+32}
    #pragma unroll
    for (int i = 0; i < 4; ++i) {
        const int bi = b[i];
        const unsigned r0 = __ballot_sync(0xFFFFFFFFu, bi & 1);
        const unsigned r1 = __ballot_sync(0xFFFFFFFFu, bi & 2);
        const unsigned r2 = __ballot_sync(0xFFFFFFFFu, bi & 4);
        const unsigned r3 = __ballot_sync(0xFFFFFFFFu, bi & 8);
        const unsigned r4 = __ballot_sync(0xFFFFFFFFu, bi & 16);
        const unsigned r5 = __ballot_sync(0xFFFFFFFFu, bi & 32);
        const unsigned rf = __ballot_sync(0xFFFFFFFFu, f[i]);

        unsigned m = (lane & 1  ? r0 : ~r0);
        m &=         (lane & 2  ? r1 : ~r1);
        m &=         (lane & 4  ? r2 : ~r2);
        m &=         (lane & 8  ? r3 : ~r3);
        m &=         (lane & 16 ? r4 : ~r4);
        const unsigned mLo = m & ~r5;
        const unsigned mHi = m &  r5;
        cl += __popc(mLo & rf) + (__popc(mLo & ~rf) << 16);
        ch += __popc(mHi & rf) + (__popc(mHi & ~rf) << 16);
    }
    cnt[g][lane][wg]      = cl;
    cnt[g][lane + 32][wg] = ch;
    asm volatile("bar.sync %0, %1;" :: "r"(g + 1), "r"(128) : "memory");  // group bar 1

    // ---- group-warp-0: merge 4 warp histograms + packed scan + weights ----
    if (wg == 0) {
        const int4 m0 = ((const int4*)cnt[g])[2 * lane];       // cnt[g][2L][0..3]
        const int4 m1 = ((const int4*)cnt[g])[2 * lane + 1];   // cnt[g][2L+1][0..3]
        const int x0 = m0.x + m0.y + m0.z + m0.w;
        const int x1 = m1.x + m1.y + m1.z + m1.w;
        const int tsum = x0 + x1;

        int incv = tsum;
        #pragma unroll
        for (int off = 1; off < 32; off <<= 1) {
            const int v = __shfl_up_sync(0xFFFFFFFFu, incv, off);
            if (lane >= off) incv += v;
        }
        const int total = __shfl_sync(0xFFFFFFFFu, incv, 31);
        const int p = total & 0xFFFF;
        const int q = total >> 16;

        int pr = incv - tsum;
        {
            const int cP = x0 & 0xFFFF, cN = x0 >> 16;
            const int PP = pr & 0xFFFF, PN = pr >> 16;
            metaf[g][2 * lane] = make_float4(
                (float)(2 * PP + cP - p),
                (float)(2 * PN + cN - q),
                (float)(2 * (PP + PN) + (cP + cN) - WLEN), 0.0f);
            pr += x0;
        }
        {
            const int cP = x1 & 0xFFFF, cN = x1 >> 16;
            const int PP = pr & 0xFFFF, PN = pr >> 16;
            metaf[g][2 * lane + 1] = make_float4(
                (float)(2 * PP + cP - p),
                (float)(2 * PN + cN - q),
                (float)(2 * (PP + PN) + (cP + cN) - WLEN), 0.0f);
        }
        if (lane == 0) totalSh[g] = total;
    }
    asm volatile("bar.sync %0, %1;" :: "r"(g + 1), "r"(128) : "memory");  // group bar 2

    // ---- per-element fp32 contributions: LDS.128 + FFMAs ----
    float app = 0.0f, ann = 0.0f, aall = 0.0f;
    #pragma unroll
    for (int i = 0; i < 4; ++i) {
        const float4 w = metaf[g][b[i]];
        if (f[i]) app += h[i] * w.x;
        else      ann += h[i] * w.y;
        aall += h[i] * w.z;
    }

    // ---- intra-warp reduce; one smem store per warp ----
    #pragma unroll
    for (int off = 16; off > 0; off >>= 1) {
        app  += __shfl_down_sync(0xFFFFFFFFu, app,  off);
        ann  += __shfl_down_sync(0xFFFFFFFFu, ann,  off);
        aall += __shfl_down_sync(0xFFFFFFFFu, aall, off);
    }
    if (lane == 0) {
        red[g][wg][0] = app;
        red[g][wg][1] = ann;
        red[g][wg][2] = aall;
    }
    __syncthreads();                                   // single full-CTA barrier

    // ---- tid0: fold all channels, write out[n] directly ----
    if (tid == 0) {
        float rowLoss = 0.0f;
        #pragma unroll
        for (int c = 0; c < 3; ++c) {
            float Ap = 0.0f, An = 0.0f, Aa = 0.0f;
            #pragma unroll
            for (int w = 0; w < GW; ++w) {
                Ap += red[c][w][0];
                An += red[c][w][1];
                Aa += red[c][w][2];
            }
            const int total = totalSh[c];
            const float pf = (float)(total & 0xFFFF);
            const float qf = (float)(total >> 16);
            const float Apn = Aa - Ap - An;
            const float c1 = (2.0f * Ap)  / (pf * (pf - 1.0f) + 1.0f);
            const float c2 = 1.0f - (2.0f * Apn) / (2.0f * pf * qf + 1.0f);
            const float c3 = (2.0f * An)  / (qf * (qf - 1.0f) + 1.0f);
            rowLoss += c1 + c2 + c3;
        }
        out[n] = rowLoss;
    }
}

extern "C" void kernel_launch(void* const* d_in, const int* in_sizes, int n_in,
                              void* d_out, int out_size)
{
    const float* a_gt = (const float*)d_in[0];
    const float* s_gt = (const float*)d_in[1];
    const float* e_gt = (const float*)d_in[2];
    const float* a_h  = (const float*)d_in[3];
    const float* s_h  = (const float*)d_in[4];
    const float* e_h  = (const float*)d_in[5];
    float* out = (float*)d_out;

    icl_kernel<<<N_ROWS, BT>>>(a_gt, s_gt, e_gt, a_h, s_h, e_h, out);
}